// round 2
// baseline (speedup 1.0000x reference)
#include <cuda_runtime.h>
#include <math.h>

#define BB 2
#define TT 2048
#define DD 1024
#define HH 16
#define DH 64
#define NREL 7

// Scratch (static device globals — no allocation)
__device__ float g_q[BB*TT*HH*DH];
__device__ float g_k[BB*TT*HH*DH];
__device__ float g_v[BB*TT*HH*DH];
__device__ float g_attn[BB*TT*HH*DH];
__device__ float g_pk[NREL*HH*DH];

// ---------------------------------------------------------------------------
// SGEMM: C[M,N] = A[M,K] @ W[K,N] + bias[N]   (row-major, M,N mult of 128,
// K mult of 16). 128x128 tile, BK=16, 256 threads, 8x8 microtile.
// ---------------------------------------------------------------------------
__global__ __launch_bounds__(256) void sgemm_bias(
    const float* __restrict__ A, const float* __restrict__ W,
    const float* __restrict__ bias, float* __restrict__ C,
    int M, int N, int K)
{
    __shared__ float As[16][136];   // transposed A tile: As[k][m] (padded)
    __shared__ float Bs[16][128];   // Bs[k][n]

    const int tid = threadIdx.x;
    const int tx = tid & 15;        // col group (8 cols each)
    const int ty = tid >> 4;        // row group (8 rows each)
    const int bm = blockIdx.y * 128;
    const int bn = blockIdx.x * 128;

    float acc[8][8];
    #pragma unroll
    for (int i = 0; i < 8; i++)
        #pragma unroll
        for (int j = 0; j < 8; j++) acc[i][j] = 0.f;

    for (int k0 = 0; k0 < K; k0 += 16) {
        // Load A tile (128x16) -> transposed smem
        #pragma unroll
        for (int it = 0; it < 2; it++) {
            int la = tid + it * 256;          // 0..511 float4 slots
            int row = la >> 2;
            int k4 = (la & 3) << 2;
            float4 v = *(const float4*)(A + (size_t)(bm + row) * K + k0 + k4);
            As[k4 + 0][row] = v.x;
            As[k4 + 1][row] = v.y;
            As[k4 + 2][row] = v.z;
            As[k4 + 3][row] = v.w;
        }
        // Load B tile (16x128) straight
        #pragma unroll
        for (int it = 0; it < 2; it++) {
            int lb = tid + it * 256;
            int kr = lb >> 5;
            int n4 = (lb & 31) << 2;
            *(float4*)(&Bs[kr][n4]) =
                *(const float4*)(W + (size_t)(k0 + kr) * N + bn + n4);
        }
        __syncthreads();

        #pragma unroll
        for (int k = 0; k < 16; k++) {
            float a[8], b[8];
            *(float4*)(a)     = *(float4*)(&As[k][ty * 8]);
            *(float4*)(a + 4) = *(float4*)(&As[k][ty * 8 + 4]);
            *(float4*)(b)     = *(float4*)(&Bs[k][tx * 8]);
            *(float4*)(b + 4) = *(float4*)(&Bs[k][tx * 8 + 4]);
            #pragma unroll
            for (int i = 0; i < 8; i++)
                #pragma unroll
                for (int j = 0; j < 8; j++)
                    acc[i][j] += a[i] * b[j];
        }
        __syncthreads();
    }

    float bb[8];
    *(float4*)(bb)     = *(const float4*)(bias + bn + tx * 8);
    *(float4*)(bb + 4) = *(const float4*)(bias + bn + tx * 8 + 4);

    #pragma unroll
    for (int i = 0; i < 8; i++) {
        int row = bm + ty * 8 + i;
        float4 o0 = make_float4(acc[i][0] + bb[0], acc[i][1] + bb[1],
                                acc[i][2] + bb[2], acc[i][3] + bb[3]);
        float4 o1 = make_float4(acc[i][4] + bb[4], acc[i][5] + bb[5],
                                acc[i][6] + bb[6], acc[i][7] + bb[7]);
        *(float4*)(C + (size_t)row * N + bn + tx * 8)     = o0;
        *(float4*)(C + (size_t)row * N + bn + tx * 8 + 4) = o1;
    }
}

// ---------------------------------------------------------------------------
// pk = pos_emb(7,1024) @ Wk(1024,1024) + bk   -> g_pk (7,1024)
// ---------------------------------------------------------------------------
__global__ void pk_gemm(const float* __restrict__ pos_emb,
                        const float* __restrict__ Wk,
                        const float* __restrict__ bk,
                        float* __restrict__ pk)
{
    int r = blockIdx.x;
    int n = blockIdx.y * 256 + threadIdx.x;
    float s = bk[n];
    const float* pe = pos_emb + r * DD;
    for (int k = 0; k < DD; k++)
        s += pe[k] * Wk[(size_t)k * DD + n];
    pk[r * DD + n] = s;
}

// ---------------------------------------------------------------------------
// Fused flash attention with TransformerXL relative bias.
// Block: 128 query rows of one (b,h); 128 threads; key tiles of 64.
// tx = tid&7 (8 keys / 8 dh columns each), ty = tid>>3 (8 rows each).
// ---------------------------------------------------------------------------
#define QS_STRIDE 132
#define KS_STRIDE 68
#define PS_STRIDE 132

__global__ __launch_bounds__(128, 2) void attn_kernel(
    const float* __restrict__ q, const float* __restrict__ k,
    const float* __restrict__ v, const float* __restrict__ pk,
    const float* __restrict__ cbias, const float* __restrict__ rbias,
    float* __restrict__ out)
{
    extern __shared__ float sm[];
    float* Qs     = sm;                      // [64 d][132] (rows 0..127 used)
    float* Ks     = Qs + 64 * QS_STRIDE;     // [64 d][68]  (keys)
    float* Vs     = Ks + 64 * KS_STRIDE;     // [64 key][68] (dh)
    float* Ps     = Vs + 64 * KS_STRIDE;     // [64 key][132] (rows)
    float* smalls = Ps + 64 * PS_STRIDE;     // [128][8]
    float* pks    = smalls + 128 * 8;        // [7][64]
    float* us     = pks + NREL * 64;         // [64]
    float* corr   = us + 64;                 // [8]

    const int tid = threadIdx.x;
    const int tx = tid & 7;
    const int ty = tid >> 3;
    const int h = blockIdx.y;
    const int b = blockIdx.z;
    const int q0 = blockIdx.x * 128;

    const float* qb = q + (size_t)b * TT * (HH * DH) + h * DH;
    const float* kb = k + (size_t)b * TT * (HH * DH) + h * DH;
    const float* vb = v + (size_t)b * TT * (HH * DH) + h * DH;

    // ---- prologue: biases, pk tile ----
    if (tid < 64) us[tid] = cbias[h * DH + tid];
    for (int i = tid; i < NREL * 64; i += 128) {
        int r = i >> 6, d = i & 63;
        pks[i] = pk[r * DD + h * DH + d];
    }
    __syncthreads();

    // ---- Q tile (128 rows x 64 d) -> transposed smem, with +content_bias ----
    #pragma unroll
    for (int it = 0; it < 16; it++) {
        int l = tid + it * 128;          // 0..2047 float4 slots
        int row = l >> 4;
        int d4 = (l & 15) << 2;
        float4 vq = *(const float4*)(qb + (size_t)(q0 + row) * (HH * DH) + d4);
        Qs[(d4 + 0) * QS_STRIDE + row] = vq.x + us[d4 + 0];
        Qs[(d4 + 1) * QS_STRIDE + row] = vq.y + us[d4 + 1];
        Qs[(d4 + 2) * QS_STRIDE + row] = vq.z + us[d4 + 2];
        Qs[(d4 + 3) * QS_STRIDE + row] = vq.w + us[d4 + 3];
    }
    // corr[r] = sum_d (rbias - cbias) * pk[r]  (compensates u baked into Qs)
    if (tid < NREL) {
        float s = 0.f;
        for (int d = 0; d < 64; d++)
            s += (rbias[h * DH + d] - us[d]) * pks[tid * 64 + d];
        corr[tid] = s;
    }
    __syncthreads();

    // ---- small[row][r] = (q_raw + rbias) . pk[r] ----
    {
        float accr[NREL];
        #pragma unroll
        for (int r = 0; r < NREL; r++) accr[r] = corr[r];
        for (int d = 0; d < 64; d++) {
            float qv = Qs[d * QS_STRIDE + tid];
            #pragma unroll
            for (int r = 0; r < NREL; r++) accr[r] += qv * pks[r * 64 + d];
        }
        #pragma unroll
        for (int r = 0; r < NREL; r++) smalls[tid * 8 + r] = accr[r];
    }
    __syncthreads();

    // ---- main loop over key tiles ----
    float m_i[8], l_i[8], O[8][8];
    #pragma unroll
    for (int i = 0; i < 8; i++) {
        m_i[i] = -1e30f; l_i[i] = 0.f;
        #pragma unroll
        for (int j = 0; j < 8; j++) O[i][j] = 0.f;
    }
    const float scale = 0.125f;   // 1/sqrt(64)

    for (int kt = 0; kt < TT; kt += 64) {
        __syncthreads();
        // load K (transposed) and V (straight)
        #pragma unroll
        for (int it = 0; it < 8; it++) {
            int l = tid + it * 128;       // 0..1023 float4 slots
            int row = l >> 4;
            int d4 = (l & 15) << 2;
            float4 vk = *(const float4*)(kb + (size_t)(kt + row) * (HH * DH) + d4);
            Ks[(d4 + 0) * KS_STRIDE + row] = vk.x;
            Ks[(d4 + 1) * KS_STRIDE + row] = vk.y;
            Ks[(d4 + 2) * KS_STRIDE + row] = vk.z;
            Ks[(d4 + 3) * KS_STRIDE + row] = vk.w;
            float4 vv = *(const float4*)(vb + (size_t)(kt + row) * (HH * DH) + d4);
            *(float4*)(&Vs[row * KS_STRIDE + d4]) = vv;
        }
        __syncthreads();

        // S = (q+u) K^T
        float S[8][8];
        #pragma unroll
        for (int i = 0; i < 8; i++)
            #pragma unroll
            for (int j = 0; j < 8; j++) S[i][j] = 0.f;

        #pragma unroll
        for (int d = 0; d < 64; d++) {
            float a[8], bf[8];
            *(float4*)(a)      = *(float4*)(&Qs[d * QS_STRIDE + ty * 8]);
            *(float4*)(a + 4)  = *(float4*)(&Qs[d * QS_STRIDE + ty * 8 + 4]);
            *(float4*)(bf)     = *(float4*)(&Ks[d * KS_STRIDE + tx * 8]);
            *(float4*)(bf + 4) = *(float4*)(&Ks[d * KS_STRIDE + tx * 8 + 4]);
            #pragma unroll
            for (int i = 0; i < 8; i++)
                #pragma unroll
                for (int j = 0; j < 8; j++)
                    S[i][j] += a[i] * bf[j];
        }

        // add relative bias + scale
        #pragma unroll
        for (int i = 0; i < 8; i++) {
            int tq = q0 + ty * 8 + i;
            const float* srow = &smalls[(ty * 8 + i) * 8];
            #pragma unroll
            for (int j = 0; j < 8; j++) {
                int tk = kt + tx * 8 + j;
                int dlt = tq - tk;
                dlt = min(3, max(-3, dlt)) + 3;
                S[i][j] = (S[i][j] + srow[dlt]) * scale;
            }
        }

        // online softmax (row = 8 lanes: tx 0..7)
        #pragma unroll
        for (int i = 0; i < 8; i++) {
            float mt = S[i][0];
            #pragma unroll
            for (int j = 1; j < 8; j++) mt = fmaxf(mt, S[i][j]);
            mt = fmaxf(mt, __shfl_xor_sync(0xffffffffu, mt, 1));
            mt = fmaxf(mt, __shfl_xor_sync(0xffffffffu, mt, 2));
            mt = fmaxf(mt, __shfl_xor_sync(0xffffffffu, mt, 4));
            float mnew = fmaxf(m_i[i], mt);
            float c = __expf(m_i[i] - mnew);
            m_i[i] = mnew;
            float ls = 0.f;
            #pragma unroll
            for (int j = 0; j < 8; j++) {
                float p = __expf(S[i][j] - mnew);
                S[i][j] = p;
                ls += p;
            }
            ls += __shfl_xor_sync(0xffffffffu, ls, 1);
            ls += __shfl_xor_sync(0xffffffffu, ls, 2);
            ls += __shfl_xor_sync(0xffffffffu, ls, 4);
            l_i[i] = l_i[i] * c + ls;
            #pragma unroll
            for (int j = 0; j < 8; j++) O[i][j] *= c;
        }

        // write P transposed: Ps[key][row]
        #pragma unroll
        for (int j = 0; j < 8; j++) {
            float4 p0 = make_float4(S[0][j], S[1][j], S[2][j], S[3][j]);
            float4 p1 = make_float4(S[4][j], S[5][j], S[6][j], S[7][j]);
            *(float4*)(&Ps[(tx * 8 + j) * PS_STRIDE + ty * 8])     = p0;
            *(float4*)(&Ps[(tx * 8 + j) * PS_STRIDE + ty * 8 + 4]) = p1;
        }
        __syncthreads();

        // O += P @ V
        #pragma unroll
        for (int kk = 0; kk < 64; kk++) {
            float a[8], bf[8];
            *(float4*)(a)      = *(float4*)(&Ps[kk * PS_STRIDE + ty * 8]);
            *(float4*)(a + 4)  = *(float4*)(&Ps[kk * PS_STRIDE + ty * 8 + 4]);
            *(float4*)(bf)     = *(float4*)(&Vs[kk * KS_STRIDE + tx * 8]);
            *(float4*)(bf + 4) = *(float4*)(&Vs[kk * KS_STRIDE + tx * 8 + 4]);
            #pragma unroll
            for (int i = 0; i < 8; i++)
                #pragma unroll
                for (int j = 0; j < 8; j++)
                    O[i][j] += a[i] * bf[j];
        }
    }

    // epilogue
    #pragma unroll
    for (int i = 0; i < 8; i++) {
        float inv = 1.f / l_i[i];
        int tq = q0 + ty * 8 + i;
        float4 o0 = make_float4(O[i][0] * inv, O[i][1] * inv,
                                O[i][2] * inv, O[i][3] * inv);
        float4 o1 = make_float4(O[i][4] * inv, O[i][5] * inv,
                                O[i][6] * inv, O[i][7] * inv);
        float* op = out + ((size_t)b * TT + tq) * (HH * DH) + h * DH + tx * 8;
        *(float4*)(op)     = o0;
        *(float4*)(op + 4) = o1;
    }
}

// ---------------------------------------------------------------------------
extern "C" void kernel_launch(void* const* d_in, const int* in_sizes, int n_in,
                              void* d_out, int out_size)
{
    const float* query   = (const float*)d_in[0];
    const float* key_    = (const float*)d_in[1];
    const float* value   = (const float*)d_in[2];
    const float* Wq      = (const float*)d_in[3];
    const float* bq      = (const float*)d_in[4];
    const float* Wk      = (const float*)d_in[5];
    const float* bk      = (const float*)d_in[6];
    const float* Wv      = (const float*)d_in[7];
    const float* bv      = (const float*)d_in[8];
    const float* Wo      = (const float*)d_in[9];
    const float* bo      = (const float*)d_in[10];
    const float* cbias   = (const float*)d_in[11];
    const float* rbias   = (const float*)d_in[12];
    const float* pos_emb = (const float*)d_in[13];

    float *q, *k, *v, *attn, *pk;
    cudaGetSymbolAddress((void**)&q, g_q);
    cudaGetSymbolAddress((void**)&k, g_k);
    cudaGetSymbolAddress((void**)&v, g_v);
    cudaGetSymbolAddress((void**)&attn, g_attn);
    cudaGetSymbolAddress((void**)&pk, g_pk);

    const int M = BB * TT;     // 4096
    const int N = HH * DH;     // 1024
    const int K = DD;          // 1024

    dim3 gg(N / 128, M / 128);  // (8, 32)
    sgemm_bias<<<gg, 256>>>(query, Wq, bq, q, M, N, K);
    sgemm_bias<<<gg, 256>>>(key_,  Wk, bk, k, M, N, K);
    sgemm_bias<<<gg, 256>>>(value, Wv, bv, v, M, N, K);
    pk_gemm<<<dim3(NREL, DD / 256), 256>>>(pos_emb, Wk, bk, pk);

    // fused attention
    size_t smem = (64 * QS_STRIDE + 64 * KS_STRIDE + 64 * KS_STRIDE +
                   64 * PS_STRIDE + 128 * 8 + NREL * 64 + 64 + 8) * sizeof(float);
    static int smem_set = 0;
    if (!smem_set) {
        cudaFuncSetAttribute(attn_kernel,
                             cudaFuncAttributeMaxDynamicSharedMemorySize, (int)smem);
        smem_set = 1;
    }
    attn_kernel<<<dim3(TT / 128, HH, BB), 128, smem>>>(q, k, v, pk, cbias, rbias, attn);

    // output projection -> d_out
    sgemm_bias<<<gg, 256>>>(attn, Wo, bo, (float*)d_out, M, N, K);
}